// round 10
// baseline (speedup 1.0000x reference)
#include <cuda_runtime.h>
#include <cstdint>

#define BATCH 4
#define SEQ   1024
#define EMB   768
#define HEADS 12
#define HDIM  64
#define BH    (BATCH*HEADS)    // 48
#define NSPL  3                // row-chunk replicas
#define NBLK  576              // grid size (48 segments * 4 jq * 3 chunks)

#define RS_ONE   (BH * HEADS * EMB)
#define G_ELEMS  (BATCH * EMB)
#define G_OFF    (NSPL * RS_ONE)

__device__ float g_Acc[NSPL * RS_ONE + G_ELEMS];
__device__ unsigned g_barCnt = 0;
__device__ unsigned g_barGen = 0;     // monotonic across replays — no reset needed

__device__ __forceinline__ void grid_barrier()
{
    __syncthreads();
    if (threadIdx.x == 0) {
        const unsigned gen = *(volatile unsigned*)&g_barGen;
        __threadfence();                       // publish this block's writes
        unsigned t = atomicAdd(&g_barCnt, 1u);
        if (t == NBLK - 1) {
            atomicExch(&g_barCnt, 0u);
            __threadfence();
            atomicAdd(&g_barGen, 1u);          // release
        } else {
            while (*(volatile unsigned*)&g_barGen == gen) __nanosleep(64);
        }
        __threadfence();
    }
    __syncthreads();
}

__global__ void __launch_bounds__(192, 4) fused_kernel(
    const float* __restrict__ value, const float* __restrict__ Wv,
    float* __restrict__ out)
{
    const int x   = blockIdx.x;
    const int tid = threadIdx.x;

    __shared__ float4 red[4][3][48];
    __shared__ float  Ws[64][65];
    __shared__ float  As[48][65];

    // ============================ PHASE 1: scan ============================
    {
        const int rc = x % 3;
        const int q  = (x / 3) & 3;
        const int bh = x / 12;
        const int b = bh / HEADS, h = bh % HEADS;
        const int col = tid % 48;
        const int rl  = tid / 48;

        if (x == 0) {    // zero G (768 float4)
            float4* Gz = (float4*)(g_Acc + G_OFF);
            #pragma unroll
            for (int i = 0; i < 4; i++)
                Gz[tid + 192 * i] = make_float4(0.f, 0.f, 0.f, 0.f);
        }

        // geometry (uniform): per-c row range [a(c), bend(c))
        const int f0 = h << 16;
        const int f1 = f0 + 65536;
        int aMin = 1 << 30, cut1 = 0, cut2 = 1 << 30, bMax = 0;
        #pragma unroll
        for (int c = 0; c < 12; c++) {
            int na = f0 - 64 * c;
            int a  = (na <= 0) ? 0 : (na + 767) / 768;
            int bd = (f1 - 64 * c - 64) / 768 + 1;
            if (bd > SEQ) bd = SEQ;
            aMin = min(aMin, a); cut1 = max(cut1, a);
            cut2 = min(cut2, bd); bMax = max(bMax, bd);
        }

        const int L  = bMax - aMin;
        const int lo = aMin + (L * rc)     / NSPL;
        const int hi = aMin + (L * (rc+1)) / NSPL;

        const float4* vp = (const float4*)(value + (size_t)b * SEQ * EMB) + q * 48 + col;

        float4 S0 = make_float4(0.f,0.f,0.f,0.f);
        float4 S1 = S0, S2 = S0;

        {   const int e = min(hi, cut1);
            for (int s = lo + rl; s < e; s += 4) {
                float4 v = vp[(size_t)s * 192];
                S0.x += v.x; S0.y += v.y; S0.z += v.z; S0.w += v.w;
            }
        }
        {   const int st = max(lo, cut1), e = min(hi, cut2);
            #pragma unroll 4
            for (int s = st + rl; s < e; s += 4) {
                float4 v = vp[(size_t)s * 192];
                S1.x += v.x; S1.y += v.y; S1.z += v.z; S1.w += v.w;
            }
        }
        {   const int st = max(lo, cut2);
            for (int s = st + rl; s < hi; s += 4) {
                float4 v = vp[(size_t)s * 192];
                S2.x += v.x; S2.y += v.y; S2.z += v.z; S2.w += v.w;
            }
        }

        red[rl][0][col] = S0;
        red[rl][1][col] = S1;
        red[rl][2][col] = S2;
        __syncthreads();

        float4 T0 = red[0][0][col], T1 = red[0][1][col], T2 = red[0][2][col];
        #pragma unroll
        for (int r = 1; r < 4; r++) {
            float4 u;
            u = red[r][0][col]; T0.x+=u.x; T0.y+=u.y; T0.z+=u.z; T0.w+=u.w;
            u = red[r][1][col]; T1.x+=u.x; T1.y+=u.y; T1.z+=u.z; T1.w+=u.w;
            u = red[r][2][col]; T2.x+=u.x; T2.y+=u.y; T2.z+=u.z; T2.w+=u.w;
        }

        float4* RS4 = (float4*)(g_Acc + (size_t)rc * RS_ONE);
        #pragma unroll
        for (int k = 0; k < 3; k++) {
            const int c = rl + 4 * k;
            int na = f0 - 64 * c;
            int a  = (na <= 0) ? 0 : (na + 767) / 768;
            int bd = (f1 - 64 * c - 64) / 768 + 1;
            if (bd > SEQ) bd = SEQ;

            float4 r = T1;
            if (a == aMin)  { r.x+=T0.x; r.y+=T0.y; r.z+=T0.z; r.w+=T0.w; }
            if (bd == bMax) { r.x+=T2.x; r.y+=T2.y; r.z+=T2.z; r.w+=T2.w; }

            RS4[(size_t)(bh * HEADS + c) * 192 + q * 48 + col] = r;
        }
    }

    grid_barrier();

    // ============================ PHASE 2: kgemm ===========================
    if (x < 144) {
        const int c  = x / 12;
        const int jt = x % 12;

        // Ws = Wv[64c..+63][jt*64..+63]: 1024 float4
        for (int f = tid; f < 1024; f += 192) {
            int r = f >> 4, c4 = f & 15;
            float4 v = *(const float4*)(Wv + (size_t)(64 * c + r) * EMB + jt * 64 + c4 * 4);
            Ws[r][c4 * 4 + 0] = v.x; Ws[r][c4 * 4 + 1] = v.y;
            Ws[r][c4 * 4 + 2] = v.z; Ws[r][c4 * 4 + 3] = v.w;
        }
        // As = sum of replicas of RS[0..47][c][jt*64..+63]: 768 float4
        for (int f = tid; f < 768; f += 192) {
            int r = f >> 4, c4 = f & 15;
            const size_t off = ((size_t)r * HEADS + c) * EMB + jt * 64 + c4 * 4;
            float4 v = *(const float4*)(g_Acc + off);
            #pragma unroll
            for (int rc = 1; rc < NSPL; rc++) {
                float4 u = *(const float4*)(g_Acc + (size_t)rc * RS_ONE + off);
                v.x += u.x; v.y += u.y; v.z += u.z; v.w += u.w;
            }
            As[r][c4 * 4 + 0] = v.x; As[r][c4 * 4 + 1] = v.y;
            As[r][c4 * 4 + 2] = v.z; As[r][c4 * 4 + 3] = v.w;
        }
        __syncthreads();

        const int tx = tid & 15;    // 4 d's
        const int ty = tid >> 4;    // 0..11 -> 4 bh's

        float acc[4][4] = {};
        #pragma unroll 8
        for (int k = 0; k < 64; k++) {
            float a[4], bb[4];
            #pragma unroll
            for (int u = 0; u < 4; u++) a[u] = As[ty * 4 + u][k];
            #pragma unroll
            for (int v = 0; v < 4; v++) bb[v] = Ws[tx * 4 + v][k];
            #pragma unroll
            for (int u = 0; u < 4; u++)
                #pragma unroll
                for (int v = 0; v < 4; v++)
                    acc[u][v] = fmaf(a[u], bb[v], acc[u][v]);
        }

        #pragma unroll
        for (int u = 0; u < 4; u++) {
            int bh = ty * 4 + u;
            int b = bh / HEADS, hh = bh % HEADS;
            float* gp = g_Acc + G_OFF + b * EMB + hh * HDIM + tx * 4;
            #pragma unroll
            for (int v = 0; v < 4; v++)
                atomicAdd(gp + v, acc[u][v]);
        }
    }

    grid_barrier();

    // =========================== PHASE 3: broadcast ========================
    {
        float4 Gv[4];
        #pragma unroll
        for (int b = 0; b < 4; b++)
            Gv[b] = ((const float4*)(g_Acc + G_OFF + b * EMB))[tid];

        for (int row = x; row < BATCH * SEQ; row += NBLK)
            ((float4*)(out + (size_t)row * EMB))[tid] = Gv[row >> 10];
    }
}

// ---------------------------------------------------------------------------
extern "C" void kernel_launch(void* const* d_in, const int* in_sizes, int n_in,
                              void* d_out, int out_size)
{
    // metadata order: key, query, value, Wk, Wq, Wv
    const float* value = (const float*)d_in[2];
    const float* Wv    = (const float*)d_in[5];
    float* out = (float*)d_out;

    fused_kernel<<<NBLK, 192>>>(value, Wv, out);
}